// round 15
// baseline (speedup 1.0000x reference)
#include <cuda_runtime.h>
#include <cuda_fp16.h>

#define NN 100000
#define EE 1000000
#define HH 64
#define GG 64
#define BN_EPS 1e-5f
#define NB_SCAN 49   // ceil(NN/2048)
#define NB_G1   782  // ceil(NN/128) gemm blocks in fused kernel
#define NB_SCT  489  // ceil((EE/8)/256) scatter blocks in fused kernel
#define NB_DEG  977  // ceil((EE/4)/256) degree blocks
#define NB_AUX  391  // ceil((NN+1)/256) aux blocks (wfrag + gstart)

// ---------------- scratch (static __device__, zero-init, self-restoring) ----------------
__device__ int      g_deg[NN];        // in-degree (reset by agg2 each run)
__device__ int      g_off[NN];        // chunk-local offsets (overwritten each run)
__device__ int      g_csr[EE];        // CSR src row per incoming edge
__device__ float    g_dinv[NN];       // rsqrt(deg+1)
__device__ __half2  g_hs[NN * 32];    // gemm output (fp16, 128B/row)
__device__ __half2  g_hb[NN * 32];    // agg1 output (fp16, gemm2 input)
__device__ float    g_pool[GG * 64];  // pooled sums (reset by k_head)
__device__ int      g_gstart[GG + 1]; // graph segment starts (overwritten)
__device__ int      g_bsum[64];       // scan chunk totals (overwritten)
__device__ int      g_pref[64];       // exclusive chunk prefixes (overwritten)
__device__ int      g_done;           // scan lookback counter (self-reset)
__device__ unsigned g_wfrag[2][2048]; // preformatted W fragments (overwritten)

// ---------------- launch 0: degree histogram ∥ (wfrag preformat + graph bounds) ----------------
__global__ void k_degree_init(const int* __restrict__ ei, const int* __restrict__ batch,
                              const float* __restrict__ W1, const float* __restrict__ W2) {
    int t = threadIdx.x;
    if (blockIdx.x < NB_DEG) {
        int e = blockIdx.x * 256 + t;
        if (e < EE / 4) {
            int4 c = ((const int4*)(ei + EE))[e];
            atomicAdd(&g_deg[c.x], 1);
            atomicAdd(&g_deg[c.y], 1);
            atomicAdd(&g_deg[c.z], 1);
            atomicAdd(&g_deg[c.w], 1);
        }
        return;
    }
    int i = (blockIdx.x - NB_DEG) * 256 + t;
    if (i < 4096) {
        int l = i >> 11;
        int o = i & 2047;
        const float* W = l ? W2 : W1;
        int reg = o & 1, lane = (o >> 1) & 31, nt = (o >> 6) & 7, ktp = o >> 9;
        int n = nt * 8 + (lane >> 2);
        int k = ktp * 16 + reg * 8 + (lane & 3) * 2;
        __half2 h = __floats2half2_rn(W[n * 64 + k], W[n * 64 + k + 1]);
        g_wfrag[l][o] = *(unsigned*)&h;
    }
    if (i <= NN) {
        int prev = (i == 0) ? -1 : batch[i - 1];
        int cur  = (i < NN) ? batch[i] : GG;
        for (int g = prev + 1; g <= cur && g <= GG; g++) g_gstart[g] = i;
    }
}

// ---------------- launch 1: per-chunk scan + dinv; last block computes chunk prefixes ----------------
__global__ void k_scan_a() {
    __shared__ int sh[256];
    __shared__ int lastflag;
    int t = threadIdx.x;
    int base = blockIdx.x * 2048 + t * 8;
    int vals[8];
    int ts = 0;
#pragma unroll
    for (int j = 0; j < 8; j++) {
        int idx = base + j;
        vals[j] = (idx < NN) ? g_deg[idx] : 0;
        if (idx < NN) g_dinv[idx] = rsqrtf((float)(vals[j] + 1));
        ts += vals[j];
    }
    sh[t] = ts;
    __syncthreads();
#pragma unroll
    for (int d = 1; d < 256; d <<= 1) {
        int v = (t >= d) ? sh[t - d] : 0;
        __syncthreads();
        sh[t] += v;
        __syncthreads();
    }
    int excl = sh[t] - ts;
    int run = 0;
#pragma unroll
    for (int j = 0; j < 8; j++) {
        int idx = base + j;
        if (idx < NN) g_off[idx] = excl + run;  // chunk-local exclusive offset
        run += vals[j];
    }
    if (t == 255) g_bsum[blockIdx.x] = sh[255];
    __threadfence();
    __syncthreads();
    if (t == 0) lastflag = (atomicAdd(&g_done, 1) == NB_SCAN - 1) ? 1 : 0;
    __syncthreads();
    if (!lastflag) return;
    __threadfence();
    __shared__ int sv[64];
    int v0 = 0;
    if (t < 64) {
        v0 = (t < NB_SCAN) ? g_bsum[t] : 0;
        sv[t] = v0;
    }
    __syncthreads();
#pragma unroll
    for (int d = 1; d < 64; d <<= 1) {
        int v = (t >= d && t < 64) ? sv[t - d] : 0;
        __syncthreads();
        if (t < 64) sv[t] += v;
        __syncthreads();
    }
    if (t < NB_SCAN) g_pref[t] = sv[t] - v0;  // exclusive
    if (t == 0) g_done = 0;                   // self-reset for graph replay
}

// ---------------- shared GEMM body: mma.sync m16n8k16 fp16 (fp32 accum) ----------------
template <bool FP16IN>
__device__ __forceinline__ void gemm_body(unsigned* shm, const void* __restrict__ Xin,
                                          const unsigned* __restrict__ wfrag,
                                          __half2* __restrict__ O, int base, int tid) {
    unsigned (*sA)[4][32][4] = (unsigned (*)[4][32][4])shm;
    unsigned* sB = shm + 4096;

#pragma unroll
    for (int i = tid; i < 512; i += 256)
        ((uint4*)sB)[i] = ((const uint4*)wfrag)[i];

    if (FP16IN) {
        const uint4* X = (const uint4*)Xin;
        for (int i = tid; i < 1024; i += 256) {
            int r = i >> 3, j = i & 7;
            int R = base + r;
            uint4 v = make_uint4(0u, 0u, 0u, 0u);
            if (R < NN) v = X[(size_t)R * 8 + j];
            int w8 = r >> 4, rr = r & 15;
            int ktp = j >> 1;
            int reg = ((rr >> 3) & 1) | ((j & 1) << 1);
            int lb = (rr & 7) * 4;
            sA[w8][ktp][lb + 0][reg] = v.x;
            sA[w8][ktp][lb + 1][reg] = v.y;
            sA[w8][ktp][lb + 2][reg] = v.z;
            sA[w8][ktp][lb + 3][reg] = v.w;
        }
    } else {
        const float4* X = (const float4*)Xin;
        for (int i = tid; i < 2048; i += 256) {
            int r = i >> 4, j = i & 15;
            int R = base + r;
            float4 v = make_float4(0.f, 0.f, 0.f, 0.f);
            if (R < NN) v = X[(size_t)R * 16 + j];
            int w8 = r >> 4, rr = r & 15;
            int ktp = j >> 2, jj = j & 3;
            int reg = ((rr >> 3) & 1) | ((jj >> 1) << 1);
            int t0 = (2 * jj) & 3;
            int lb = (rr & 7) * 4;
            __half2 h0 = __floats2half2_rn(v.x, v.y);
            __half2 h1 = __floats2half2_rn(v.z, v.w);
            sA[w8][ktp][lb + t0][reg]     = *(unsigned*)&h0;
            sA[w8][ktp][lb + t0 + 1][reg] = *(unsigned*)&h1;
        }
    }
    __syncthreads();

    int lane = tid & 31;
    int w = tid >> 5;
    float d[8][4];
#pragma unroll
    for (int nt = 0; nt < 8; nt++)
#pragma unroll
        for (int j = 0; j < 4; j++) d[nt][j] = 0.f;

#pragma unroll
    for (int ktp = 0; ktp < 4; ktp++) {
        uint4 a = *(const uint4*)&sA[w][ktp][lane][0];
#pragma unroll
        for (int nt = 0; nt < 8; nt++) {
            uint2 b = *(const uint2*)&sB[(((ktp << 3) + nt) << 6) + (lane << 1)];
            asm volatile(
                "mma.sync.aligned.m16n8k16.row.col.f32.f16.f16.f32 "
                "{%0,%1,%2,%3}, {%4,%5,%6,%7}, {%8,%9}, {%0,%1,%2,%3};"
                : "+f"(d[nt][0]), "+f"(d[nt][1]), "+f"(d[nt][2]), "+f"(d[nt][3])
                : "r"(a.x), "r"(a.y), "r"(a.z), "r"(a.w), "r"(b.x), "r"(b.y));
        }
    }

    __syncthreads();
    unsigned* sD = shm;
    int g = lane >> 2, t4 = lane & 3;
    int rl0 = w * 16 + g, rl1 = rl0 + 8;
    int row0 = base + rl0, row1 = base + rl1;
    float dv0 = (row0 < NN) ? g_dinv[row0] : 0.f;
    float dv1 = (row1 < NN) ? g_dinv[row1] : 0.f;
#pragma unroll
    for (int nt = 0; nt < 8; nt++) {
        int cp = nt * 4 + t4;
        __half2 h0 = __floats2half2_rn(d[nt][0] * dv0, d[nt][1] * dv0);
        __half2 h1 = __floats2half2_rn(d[nt][2] * dv1, d[nt][3] * dv1);
        sD[rl0 * 36 + cp] = *(unsigned*)&h0;
        sD[rl1 * 36 + cp] = *(unsigned*)&h1;
    }
    __syncthreads();
#pragma unroll
    for (int i = tid; i < 1024; i += 256) {
        int r = i >> 3, col = i & 7;
        int R = base + r;
        if (R < NN)
            ((uint4*)O)[(size_t)R * 8 + col] = *(const uint4*)&sD[r * 36 + col * 4];
    }
}

// ---------------- launch 2: gemm1 (blocks < NB_G1) ∥ CSR scatter (8 edges/thread) ----------------
__global__ void __launch_bounds__(256) k_gemm1_scatter(
    const float4* __restrict__ X, const unsigned* __restrict__ wfrag,
    __half2* __restrict__ O, const int* __restrict__ ei) {
    __shared__ unsigned shm[6144];
    if (blockIdx.x >= NB_G1) {
        int e = (blockIdx.x - NB_G1) * 256 + threadIdx.x;  // int8-group id
        if (e < EE / 8) {
            const int4* r4 = (const int4*)ei;
            const int4* c4 = (const int4*)(ei + EE);
            int4 r0 = r4[2 * e], r1 = r4[2 * e + 1];
            int4 c0 = c4[2 * e], c1 = c4[2 * e + 1];
            g_csr[atomicAdd(&g_off[c0.x], 1) + g_pref[c0.x >> 11]] = r0.x;
            g_csr[atomicAdd(&g_off[c0.y], 1) + g_pref[c0.y >> 11]] = r0.y;
            g_csr[atomicAdd(&g_off[c0.z], 1) + g_pref[c0.z >> 11]] = r0.z;
            g_csr[atomicAdd(&g_off[c0.w], 1) + g_pref[c0.w >> 11]] = r0.w;
            g_csr[atomicAdd(&g_off[c1.x], 1) + g_pref[c1.x >> 11]] = r1.x;
            g_csr[atomicAdd(&g_off[c1.y], 1) + g_pref[c1.y >> 11]] = r1.y;
            g_csr[atomicAdd(&g_off[c1.z], 1) + g_pref[c1.z >> 11]] = r1.z;
            g_csr[atomicAdd(&g_off[c1.w], 1) + g_pref[c1.w >> 11]] = r1.w;
        }
        return;
    }
    gemm_body<false>(shm, X, wfrag, O, blockIdx.x * 128, threadIdx.x);
}

// ---------------- launch 4: gemm2 (fp16 input) ----------------
__global__ void __launch_bounds__(256) k_gemm2(
    const __half2* __restrict__ X, const unsigned* __restrict__ wfrag,
    __half2* __restrict__ O) {
    __shared__ unsigned shm[6144];
    gemm_body<true>(shm, X, wfrag, O, blockIdx.x * 128, threadIdx.x);
}

// ---------------- aggregation + bias + BN + ReLU (warp per node, MLP-8 loop) ----------------
template <bool POOL, int NODES_PER_BLK>
__global__ void k_agg(const __half2* __restrict__ hs, __half2* __restrict__ out,
                      const int* __restrict__ batch,
                      const float* __restrict__ bias,
                      const float* __restrict__ bng, const float* __restrict__ bnb,
                      const float* __restrict__ bnm, const float* __restrict__ bnv) {
    __shared__ float sp[2][64];
    int t = threadIdx.x;
    int w0 = blockIdx.x * NODES_PER_BLK;
    int gid0 = 0, gidL = 0;
    if (POOL) {
        if (t < 128) sp[t >> 6][t & 63] = 0.f;
        gid0 = batch[w0];
        int wl = w0 + NODES_PER_BLK - 1;
        gidL = batch[wl < NN ? wl : NN - 1];
        __syncthreads();
    }
    int w = w0 + (t >> 5);
    int l = t & 31;
    if (w < NN) {
        float2 acc = __half22float2(hs[(size_t)w * 32 + l]);  // self loop
        int cnt = g_deg[w];
        int s = g_off[w] + g_pref[w >> 11] - cnt;  // global start
        int i = 0;
        for (; i + 8 <= cnt; i += 8) {
            int r0 = g_csr[s + i + 0];
            int r1 = g_csr[s + i + 1];
            int r2 = g_csr[s + i + 2];
            int r3 = g_csr[s + i + 3];
            int r4 = g_csr[s + i + 4];
            int r5 = g_csr[s + i + 5];
            int r6 = g_csr[s + i + 6];
            int r7 = g_csr[s + i + 7];
            float2 a0 = __half22float2(hs[(size_t)r0 * 32 + l]);
            float2 a1 = __half22float2(hs[(size_t)r1 * 32 + l]);
            float2 a2 = __half22float2(hs[(size_t)r2 * 32 + l]);
            float2 a3 = __half22float2(hs[(size_t)r3 * 32 + l]);
            float2 a4 = __half22float2(hs[(size_t)r4 * 32 + l]);
            float2 a5 = __half22float2(hs[(size_t)r5 * 32 + l]);
            float2 a6 = __half22float2(hs[(size_t)r6 * 32 + l]);
            float2 a7 = __half22float2(hs[(size_t)r7 * 32 + l]);
            acc.x += ((a0.x + a1.x) + (a2.x + a3.x)) + ((a4.x + a5.x) + (a6.x + a7.x));
            acc.y += ((a0.y + a1.y) + (a2.y + a3.y)) + ((a4.y + a5.y) + (a6.y + a7.y));
        }
        for (; i + 4 <= cnt; i += 4) {
            int r0 = g_csr[s + i + 0];
            int r1 = g_csr[s + i + 1];
            int r2 = g_csr[s + i + 2];
            int r3 = g_csr[s + i + 3];
            float2 a0 = __half22float2(hs[(size_t)r0 * 32 + l]);
            float2 a1 = __half22float2(hs[(size_t)r1 * 32 + l]);
            float2 a2 = __half22float2(hs[(size_t)r2 * 32 + l]);
            float2 a3 = __half22float2(hs[(size_t)r3 * 32 + l]);
            acc.x += (a0.x + a1.x) + (a2.x + a3.x);
            acc.y += (a0.y + a1.y) + (a2.y + a3.y);
        }
        for (; i < cnt; i++) {
            float2 a = __half22float2(hs[(size_t)g_csr[s + i] * 32 + l]);
            acc.x += a.x;
            acc.y += a.y;
        }
        if (POOL && l == 0) g_deg[w] = 0;  // self-restore for next run
        float dv = g_dinv[w];
        int c = 2 * l;
        float px = fmaf(acc.x, dv, bias[c]);
        float py = fmaf(acc.y, dv, bias[c + 1]);
        float sx = bng[c] * rsqrtf(bnv[c] + BN_EPS);
        float sy = bng[c + 1] * rsqrtf(bnv[c + 1] + BN_EPS);
        float ox = fmaxf(0.f, fmaf(px - bnm[c], sx, bnb[c]));
        float oy = fmaxf(0.f, fmaf(py - bnm[c + 1], sy, bnb[c + 1]));
        if (!POOL) {
            out[(size_t)w * 32 + l] = __floats2half2_rn(ox, oy);
        } else {
            int gid = batch[w];
            int slot = gid - gid0;
            if (slot < 2) {
                atomicAdd(&sp[slot][c], ox);
                atomicAdd(&sp[slot][c + 1], oy);
            } else {
                atomicAdd(&g_pool[gid * 64 + c], ox);
                atomicAdd(&g_pool[gid * 64 + c + 1], oy);
            }
        }
    }
    if (POOL) {
        __syncthreads();
        if (t < 128) {
            int s2 = t >> 6, ch = t & 63;
            int gg = gid0 + s2;
            if (gg <= gidL && gg < GG) atomicAdd(&g_pool[gg * 64 + ch], sp[s2][ch]);
        }
    }
}

// ---------------- MLP head (+ g_pool self-restore) ----------------
__global__ void k_head(const float* __restrict__ l1W, const float* __restrict__ l1b,
                       const float* __restrict__ l2W, const float* __restrict__ l2b,
                       float* __restrict__ out) {
    __shared__ float sW1[32 * 64];
    __shared__ float sW2[32];
    __shared__ float sB1[32];
    int t = threadIdx.x;  // 64 threads
    for (int i = t; i < 2048; i += 64) sW1[i] = l1W[i];
    if (t < 32) { sW2[t] = l2W[t]; sB1[t] = l1b[t]; }
    __syncthreads();
    if (t < GG) {
        int g = t;
        int cnt = g_gstart[g + 1] - g_gstart[g];
        float inv = 1.f / fmaxf((float)cnt, 1.f);
        float p[64];
#pragma unroll
        for (int k = 0; k < 64; k++) p[k] = g_pool[g * 64 + k] * inv;
        float o = l2b[0];
#pragma unroll 4
        for (int j = 0; j < 32; j++) {
            float hsum = sB1[j];
#pragma unroll
            for (int k = 0; k < 64; k++) hsum = fmaf(p[k], sW1[j * 64 + k], hsum);
            o = fmaf(fmaxf(hsum, 0.f), sW2[j], o);
        }
        out[g] = o;
    }
    __syncthreads();
    for (int i = t; i < GG * 64; i += 64) g_pool[i] = 0.f;  // self-restore
}

// ---------------- launch ----------------
extern "C" void kernel_launch(void* const* d_in, const int* in_sizes, int n_in,
                              void* d_out, int out_size) {
    const float* x      = (const float*)d_in[0];
    const int*   ei     = (const int*)d_in[1];
    const int*   batch  = (const int*)d_in[2];
    const float* W1     = (const float*)d_in[3];
    const float* b1     = (const float*)d_in[4];
    const float* W2     = (const float*)d_in[5];
    const float* b2     = (const float*)d_in[6];
    const float* bn1g   = (const float*)d_in[7];
    const float* bn1b   = (const float*)d_in[8];
    const float* bn1m   = (const float*)d_in[9];
    const float* bn1v   = (const float*)d_in[10];
    const float* bn2g   = (const float*)d_in[11];
    const float* bn2b   = (const float*)d_in[12];
    const float* bn2m   = (const float*)d_in[13];
    const float* bn2v   = (const float*)d_in[14];
    const float* l1W    = (const float*)d_in[15];
    const float* l1b    = (const float*)d_in[16];
    const float* l2W    = (const float*)d_in[17];
    const float* l2b    = (const float*)d_in[18];
    float* out = (float*)d_out;

    __half2 *hs, *hb;
    unsigned* wfrag;
    cudaGetSymbolAddress((void**)&hs, g_hs);
    cudaGetSymbolAddress((void**)&hb, g_hb);
    cudaGetSymbolAddress((void**)&wfrag, g_wfrag);

    k_degree_init<<<NB_DEG + NB_AUX, 256>>>(ei, batch, W1, W2);                   // 0
    k_scan_a<<<NB_SCAN, 256>>>();                                                  // 1 (+prefixes)
    k_gemm1_scatter<<<NB_G1 + NB_SCT, 256>>>((const float4*)x, wfrag, hs, ei);     // 2
    k_agg<false, 8><<<(NN + 7) / 8, 256>>>(hs, hb, batch, b1, bn1g, bn1b, bn1m, bn1v);   // 3 <- ncu
    k_gemm2<<<NB_G1, 256>>>(hb, wfrag + 2048, hs);                                        // 4
    k_agg<true, 16><<<NN / 16, 512>>>(hs, nullptr, batch, b2, bn2g, bn2b, bn2m, bn2v);    // 5
    k_head<<<1, 64>>>(l1W, l1b, l2W, l2b, out);                                    // 6
}

// round 16
// speedup vs baseline: 1.0398x; 1.0398x over previous
#include <cuda_runtime.h>
#include <cuda_fp16.h>

#define NN 100000
#define EE 1000000
#define HH 64
#define GG 64
#define BN_EPS 1e-5f
#define NB_SCAN 49   // ceil(NN/2048)
#define NB_G1   782  // ceil(NN/128) gemm blocks in fused kernel
#define NB_SCT  489  // ceil((EE/8)/256) scatter blocks in fused kernel
#define NB_DEG  977  // ceil((EE/4)/256) degree blocks
#define NB_AUX  391  // ceil((NN+1)/256) aux blocks (wfrag + gstart)

// ---------------- scratch (static __device__, zero-init, self-restoring) ----------------
__device__ int      g_deg[NN];        // in-degree (reset by agg2 each run)
__device__ int      g_off[NN];        // chunk-local offsets (overwritten each run)
__device__ int      g_csr[EE];        // CSR src row per incoming edge
__device__ float    g_dinv[NN];       // rsqrt(deg+1)
__device__ __half2  g_hs[NN * 32];    // gemm output (fp16, 128B/row)
__device__ __half2  g_hb[NN * 32];    // agg1 output (fp16, gemm2 input)
__device__ float    g_pool[GG * 64];  // pooled sums (reset by k_head)
__device__ int      g_gstart[GG + 1]; // graph segment starts (overwritten)
__device__ int      g_bsum[64];       // scan chunk totals (overwritten)
__device__ int      g_pref[64];       // exclusive chunk prefixes (overwritten)
__device__ int      g_done;           // scan lookback counter (self-reset)
__device__ unsigned g_wfrag[2][2048]; // preformatted W fragments (overwritten)

// ---------------- launch 0: degree histogram ∥ (wfrag preformat + graph bounds) ----------------
__global__ void k_degree_init(const int* __restrict__ ei, const int* __restrict__ batch,
                              const float* __restrict__ W1, const float* __restrict__ W2) {
    int t = threadIdx.x;
    if (blockIdx.x < NB_DEG) {
        int e = blockIdx.x * 256 + t;
        if (e < EE / 4) {
            int4 c = ((const int4*)(ei + EE))[e];
            atomicAdd(&g_deg[c.x], 1);
            atomicAdd(&g_deg[c.y], 1);
            atomicAdd(&g_deg[c.z], 1);
            atomicAdd(&g_deg[c.w], 1);
        }
        return;
    }
    int i = (blockIdx.x - NB_DEG) * 256 + t;
    if (i < 4096) {
        int l = i >> 11;
        int o = i & 2047;
        const float* W = l ? W2 : W1;
        int reg = o & 1, lane = (o >> 1) & 31, nt = (o >> 6) & 7, ktp = o >> 9;
        int n = nt * 8 + (lane >> 2);
        int k = ktp * 16 + reg * 8 + (lane & 3) * 2;
        __half2 h = __floats2half2_rn(W[n * 64 + k], W[n * 64 + k + 1]);
        g_wfrag[l][o] = *(unsigned*)&h;
    }
    if (i <= NN) {
        int prev = (i == 0) ? -1 : batch[i - 1];
        int cur  = (i < NN) ? batch[i] : GG;
        for (int g = prev + 1; g <= cur && g <= GG; g++) g_gstart[g] = i;
    }
}

// ---------------- launch 1: per-chunk scan + dinv; last block computes chunk prefixes ----------------
__global__ void k_scan_a() {
    __shared__ int sh[256];
    __shared__ int lastflag;
    int t = threadIdx.x;
    int base = blockIdx.x * 2048 + t * 8;
    int vals[8];
    int ts = 0;
#pragma unroll
    for (int j = 0; j < 8; j++) {
        int idx = base + j;
        vals[j] = (idx < NN) ? g_deg[idx] : 0;
        if (idx < NN) g_dinv[idx] = rsqrtf((float)(vals[j] + 1));
        ts += vals[j];
    }
    sh[t] = ts;
    __syncthreads();
#pragma unroll
    for (int d = 1; d < 256; d <<= 1) {
        int v = (t >= d) ? sh[t - d] : 0;
        __syncthreads();
        sh[t] += v;
        __syncthreads();
    }
    int excl = sh[t] - ts;
    int run = 0;
#pragma unroll
    for (int j = 0; j < 8; j++) {
        int idx = base + j;
        if (idx < NN) g_off[idx] = excl + run;  // chunk-local exclusive offset
        run += vals[j];
    }
    if (t == 255) g_bsum[blockIdx.x] = sh[255];
    __threadfence();
    __syncthreads();
    if (t == 0) lastflag = (atomicAdd(&g_done, 1) == NB_SCAN - 1) ? 1 : 0;
    __syncthreads();
    if (!lastflag) return;
    __threadfence();
    __shared__ int sv[64];
    int v0 = 0;
    if (t < 64) {
        v0 = (t < NB_SCAN) ? g_bsum[t] : 0;
        sv[t] = v0;
    }
    __syncthreads();
#pragma unroll
    for (int d = 1; d < 64; d <<= 1) {
        int v = (t >= d && t < 64) ? sv[t - d] : 0;
        __syncthreads();
        if (t < 64) sv[t] += v;
        __syncthreads();
    }
    if (t < NB_SCAN) g_pref[t] = sv[t] - v0;  // exclusive
    if (t == 0) g_done = 0;                   // self-reset for graph replay
}

// ---------------- shared GEMM body: mma.sync m16n8k16 fp16 (fp32 accum) ----------------
template <bool FP16IN>
__device__ __forceinline__ void gemm_body(unsigned* shm, const void* __restrict__ Xin,
                                          const unsigned* __restrict__ wfrag,
                                          __half2* __restrict__ O, int base, int tid) {
    unsigned (*sA)[4][32][4] = (unsigned (*)[4][32][4])shm;
    unsigned* sB = shm + 4096;

#pragma unroll
    for (int i = tid; i < 512; i += 256)
        ((uint4*)sB)[i] = ((const uint4*)wfrag)[i];

    if (FP16IN) {
        const uint4* X = (const uint4*)Xin;
        for (int i = tid; i < 1024; i += 256) {
            int r = i >> 3, j = i & 7;
            int R = base + r;
            uint4 v = make_uint4(0u, 0u, 0u, 0u);
            if (R < NN) v = X[(size_t)R * 8 + j];
            int w8 = r >> 4, rr = r & 15;
            int ktp = j >> 1;
            int reg = ((rr >> 3) & 1) | ((j & 1) << 1);
            int lb = (rr & 7) * 4;
            sA[w8][ktp][lb + 0][reg] = v.x;
            sA[w8][ktp][lb + 1][reg] = v.y;
            sA[w8][ktp][lb + 2][reg] = v.z;
            sA[w8][ktp][lb + 3][reg] = v.w;
        }
    } else {
        const float4* X = (const float4*)Xin;
        for (int i = tid; i < 2048; i += 256) {
            int r = i >> 4, j = i & 15;
            int R = base + r;
            float4 v = make_float4(0.f, 0.f, 0.f, 0.f);
            if (R < NN) v = X[(size_t)R * 16 + j];
            int w8 = r >> 4, rr = r & 15;
            int ktp = j >> 2, jj = j & 3;
            int reg = ((rr >> 3) & 1) | ((jj >> 1) << 1);
            int t0 = (2 * jj) & 3;
            int lb = (rr & 7) * 4;
            __half2 h0 = __floats2half2_rn(v.x, v.y);
            __half2 h1 = __floats2half2_rn(v.z, v.w);
            sA[w8][ktp][lb + t0][reg]     = *(unsigned*)&h0;
            sA[w8][ktp][lb + t0 + 1][reg] = *(unsigned*)&h1;
        }
    }
    __syncthreads();

    int lane = tid & 31;
    int w = tid >> 5;
    float d[8][4];
#pragma unroll
    for (int nt = 0; nt < 8; nt++)
#pragma unroll
        for (int j = 0; j < 4; j++) d[nt][j] = 0.f;

#pragma unroll
    for (int ktp = 0; ktp < 4; ktp++) {
        uint4 a = *(const uint4*)&sA[w][ktp][lane][0];
#pragma unroll
        for (int nt = 0; nt < 8; nt++) {
            uint2 b = *(const uint2*)&sB[(((ktp << 3) + nt) << 6) + (lane << 1)];
            asm volatile(
                "mma.sync.aligned.m16n8k16.row.col.f32.f16.f16.f32 "
                "{%0,%1,%2,%3}, {%4,%5,%6,%7}, {%8,%9}, {%0,%1,%2,%3};"
                : "+f"(d[nt][0]), "+f"(d[nt][1]), "+f"(d[nt][2]), "+f"(d[nt][3])
                : "r"(a.x), "r"(a.y), "r"(a.z), "r"(a.w), "r"(b.x), "r"(b.y));
        }
    }

    __syncthreads();
    unsigned* sD = shm;
    int g = lane >> 2, t4 = lane & 3;
    int rl0 = w * 16 + g, rl1 = rl0 + 8;
    int row0 = base + rl0, row1 = base + rl1;
    float dv0 = (row0 < NN) ? g_dinv[row0] : 0.f;
    float dv1 = (row1 < NN) ? g_dinv[row1] : 0.f;
#pragma unroll
    for (int nt = 0; nt < 8; nt++) {
        int cp = nt * 4 + t4;
        __half2 h0 = __floats2half2_rn(d[nt][0] * dv0, d[nt][1] * dv0);
        __half2 h1 = __floats2half2_rn(d[nt][2] * dv1, d[nt][3] * dv1);
        sD[rl0 * 36 + cp] = *(unsigned*)&h0;
        sD[rl1 * 36 + cp] = *(unsigned*)&h1;
    }
    __syncthreads();
#pragma unroll
    for (int i = tid; i < 1024; i += 256) {
        int r = i >> 3, col = i & 7;
        int R = base + r;
        if (R < NN)
            ((uint4*)O)[(size_t)R * 8 + col] = *(const uint4*)&sD[r * 36 + col * 4];
    }
}

// ---------------- launch 2: gemm1 (blocks < NB_G1) ∥ CSR scatter (8 edges/thread) ----------------
__global__ void __launch_bounds__(256) k_gemm1_scatter(
    const float4* __restrict__ X, const unsigned* __restrict__ wfrag,
    __half2* __restrict__ O, const int* __restrict__ ei) {
    __shared__ unsigned shm[6144];
    if (blockIdx.x >= NB_G1) {
        int e = (blockIdx.x - NB_G1) * 256 + threadIdx.x;  // int8-group id
        if (e < EE / 8) {
            const int4* r4 = (const int4*)ei;
            const int4* c4 = (const int4*)(ei + EE);
            int4 r0 = r4[2 * e], r1 = r4[2 * e + 1];
            int4 c0 = c4[2 * e], c1 = c4[2 * e + 1];
            g_csr[atomicAdd(&g_off[c0.x], 1) + g_pref[c0.x >> 11]] = r0.x;
            g_csr[atomicAdd(&g_off[c0.y], 1) + g_pref[c0.y >> 11]] = r0.y;
            g_csr[atomicAdd(&g_off[c0.z], 1) + g_pref[c0.z >> 11]] = r0.z;
            g_csr[atomicAdd(&g_off[c0.w], 1) + g_pref[c0.w >> 11]] = r0.w;
            g_csr[atomicAdd(&g_off[c1.x], 1) + g_pref[c1.x >> 11]] = r1.x;
            g_csr[atomicAdd(&g_off[c1.y], 1) + g_pref[c1.y >> 11]] = r1.y;
            g_csr[atomicAdd(&g_off[c1.z], 1) + g_pref[c1.z >> 11]] = r1.z;
            g_csr[atomicAdd(&g_off[c1.w], 1) + g_pref[c1.w >> 11]] = r1.w;
        }
        return;
    }
    gemm_body<false>(shm, X, wfrag, O, blockIdx.x * 128, threadIdx.x);
}

// ---------------- launch 4: gemm2 (fp16 input) ----------------
__global__ void __launch_bounds__(256) k_gemm2(
    const __half2* __restrict__ X, const unsigned* __restrict__ wfrag,
    __half2* __restrict__ O) {
    __shared__ unsigned shm[6144];
    gemm_body<true>(shm, X, wfrag, O, blockIdx.x * 128, threadIdx.x);
}

// ---------------- aggregation + bias + BN + ReLU (warp per node) ----------------
// Inner loop: 4 edges/iter, scalar idx loads, depth-2 fp16 pairwise tree -> fp32 acc.
template <bool POOL, int NODES_PER_BLK>
__global__ void k_agg(const __half2* __restrict__ hs, __half2* __restrict__ out,
                      const int* __restrict__ batch,
                      const float* __restrict__ bias,
                      const float* __restrict__ bng, const float* __restrict__ bnb,
                      const float* __restrict__ bnm, const float* __restrict__ bnv) {
    __shared__ float sp[2][64];
    int t = threadIdx.x;
    int w0 = blockIdx.x * NODES_PER_BLK;
    int gid0 = 0, gidL = 0;
    if (POOL) {
        if (t < 128) sp[t >> 6][t & 63] = 0.f;
        gid0 = batch[w0];
        int wl = w0 + NODES_PER_BLK - 1;
        gidL = batch[wl < NN ? wl : NN - 1];
        __syncthreads();
    }
    int w = w0 + (t >> 5);
    int l = t & 31;
    if (w < NN) {
        const __half2* hl = hs + l;  // lane-fixed column base
        float2 acc = __half22float2(hl[(size_t)w * 32]);  // self loop
        int cnt = g_deg[w];
        int s = g_off[w] + g_pref[w >> 11] - cnt;  // global start
        int i = 0;
        for (; i + 4 <= cnt; i += 4) {
            int r0 = g_csr[s + i + 0];
            int r1 = g_csr[s + i + 1];
            int r2 = g_csr[s + i + 2];
            int r3 = g_csr[s + i + 3];
            __half2 h0 = hl[(size_t)r0 * 32];
            __half2 h1 = hl[(size_t)r1 * 32];
            __half2 h2 = hl[(size_t)r2 * 32];
            __half2 h3 = hl[(size_t)r3 * 32];
            __half2 p = __hadd2(__hadd2(h0, h1), __hadd2(h2, h3));  // depth-2 fp16 tree
            float2 f = __half22float2(p);
            acc.x += f.x;
            acc.y += f.y;
        }
        for (; i < cnt; i++) {
            float2 a = __half22float2(hl[(size_t)g_csr[s + i] * 32]);
            acc.x += a.x;
            acc.y += a.y;
        }
        if (POOL && l == 0) g_deg[w] = 0;  // self-restore for next run
        float dv = g_dinv[w];
        int c = 2 * l;
        float px = fmaf(acc.x, dv, bias[c]);
        float py = fmaf(acc.y, dv, bias[c + 1]);
        float sx = bng[c] * rsqrtf(bnv[c] + BN_EPS);
        float sy = bng[c + 1] * rsqrtf(bnv[c + 1] + BN_EPS);
        float ox = fmaxf(0.f, fmaf(px - bnm[c], sx, bnb[c]));
        float oy = fmaxf(0.f, fmaf(py - bnm[c + 1], sy, bnb[c + 1]));
        if (!POOL) {
            out[(size_t)w * 32 + l] = __floats2half2_rn(ox, oy);
        } else {
            int gid = batch[w];
            int slot = gid - gid0;
            if (slot < 2) {
                atomicAdd(&sp[slot][c], ox);
                atomicAdd(&sp[slot][c + 1], oy);
            } else {
                atomicAdd(&g_pool[gid * 64 + c], ox);
                atomicAdd(&g_pool[gid * 64 + c + 1], oy);
            }
        }
    }
    if (POOL) {
        __syncthreads();
        if (t < 128) {
            int s2 = t >> 6, ch = t & 63;
            int gg = gid0 + s2;
            if (gg <= gidL && gg < GG) atomicAdd(&g_pool[gg * 64 + ch], sp[s2][ch]);
        }
    }
}

// ---------------- MLP head (+ g_pool self-restore) ----------------
__global__ void k_head(const float* __restrict__ l1W, const float* __restrict__ l1b,
                       const float* __restrict__ l2W, const float* __restrict__ l2b,
                       float* __restrict__ out) {
    __shared__ float sW1[32 * 64];
    __shared__ float sW2[32];
    __shared__ float sB1[32];
    int t = threadIdx.x;  // 64 threads
    for (int i = t; i < 2048; i += 64) sW1[i] = l1W[i];
    if (t < 32) { sW2[t] = l2W[t]; sB1[t] = l1b[t]; }
    __syncthreads();
    if (t < GG) {
        int g = t;
        int cnt = g_gstart[g + 1] - g_gstart[g];
        float inv = 1.f / fmaxf((float)cnt, 1.f);
        float p[64];
#pragma unroll
        for (int k = 0; k < 64; k++) p[k] = g_pool[g * 64 + k] * inv;
        float o = l2b[0];
#pragma unroll 4
        for (int j = 0; j < 32; j++) {
            float hsum = sB1[j];
#pragma unroll
            for (int k = 0; k < 64; k++) hsum = fmaf(p[k], sW1[j * 64 + k], hsum);
            o = fmaf(fmaxf(hsum, 0.f), sW2[j], o);
        }
        out[g] = o;
    }
    __syncthreads();
    for (int i = t; i < GG * 64; i += 64) g_pool[i] = 0.f;  // self-restore
}

// ---------------- launch ----------------
extern "C" void kernel_launch(void* const* d_in, const int* in_sizes, int n_in,
                              void* d_out, int out_size) {
    const float* x      = (const float*)d_in[0];
    const int*   ei     = (const int*)d_in[1];
    const int*   batch  = (const int*)d_in[2];
    const float* W1     = (const float*)d_in[3];
    const float* b1     = (const float*)d_in[4];
    const float* W2     = (const float*)d_in[5];
    const float* b2     = (const float*)d_in[6];
    const float* bn1g   = (const float*)d_in[7];
    const float* bn1b   = (const float*)d_in[8];
    const float* bn1m   = (const float*)d_in[9];
    const float* bn1v   = (const float*)d_in[10];
    const float* bn2g   = (const float*)d_in[11];
    const float* bn2b   = (const float*)d_in[12];
    const float* bn2m   = (const float*)d_in[13];
    const float* bn2v   = (const float*)d_in[14];
    const float* l1W    = (const float*)d_in[15];
    const float* l1b    = (const float*)d_in[16];
    const float* l2W    = (const float*)d_in[17];
    const float* l2b    = (const float*)d_in[18];
    float* out = (float*)d_out;

    __half2 *hs, *hb;
    unsigned* wfrag;
    cudaGetSymbolAddress((void**)&hs, g_hs);
    cudaGetSymbolAddress((void**)&hb, g_hb);
    cudaGetSymbolAddress((void**)&wfrag, g_wfrag);

    k_degree_init<<<NB_DEG + NB_AUX, 256>>>(ei, batch, W1, W2);                   // 0
    k_scan_a<<<NB_SCAN, 256>>>();                                                  // 1 (+prefixes)
    k_gemm1_scatter<<<NB_G1 + NB_SCT, 256>>>((const float4*)x, wfrag, hs, ei);     // 2
    k_agg<false, 8><<<(NN + 7) / 8, 256>>>(hs, hb, batch, b1, bn1g, bn1b, bn1m, bn1v);   // 3 <- ncu
    k_gemm2<<<NB_G1, 256>>>(hb, wfrag + 2048, hs);                                        // 4
    k_agg<true, 16><<<NN / 16, 512>>>(hs, nullptr, batch, b2, bn2g, bn2b, bn2m, bn2v);    // 5
    k_head<<<1, 64>>>(l1W, l1b, l2W, l2b, out);                                    // 6
}

// round 17
// speedup vs baseline: 1.0575x; 1.0170x over previous
#include <cuda_runtime.h>
#include <cuda_fp16.h>

#define NN 100000
#define EE 1000000
#define HH 64
#define GG 64
#define BN_EPS 1e-5f
#define NB_SCAN 49   // ceil(NN/2048)
#define NB_G1   782  // ceil(NN/128) gemm blocks in fused kernel
#define NB_SCT  489  // ceil((EE/8)/256) scatter blocks in fused kernel
#define NB_DEG  977  // ceil((EE/4)/256) degree blocks
#define NB_AUX  391  // ceil((NN+1)/256) aux blocks

// ---------------- scratch (static __device__, zero-init, self-restoring) ----------------
__device__ int      g_deg[NN];        // in-degree (reset by agg2 each run)
__device__ int      g_off[NN];        // chunk-local offsets (overwritten each run)
__device__ int      g_csr[EE];        // CSR src row per incoming edge
__device__ float    g_dinv[NN];       // rsqrt(deg+1)
__device__ __half2  g_hs[NN * 32];    // gemm output (fp16, 128B/row)
__device__ __half2  g_hb[NN * 32];    // agg1 output (fp16, gemm2 input)
__device__ float    g_pool[GG * 64];  // pooled sums (reset by k_head)
__device__ int      g_gstart[GG + 1]; // graph segment starts (overwritten)
__device__ int      g_bsum[64];       // scan chunk totals (overwritten)
__device__ int      g_pref[64];       // exclusive chunk prefixes (overwritten)
__device__ int      g_done;           // scan lookback counter (self-reset)
__device__ unsigned g_wfrag[2][2048]; // preformatted W fragments (overwritten)
__device__ float    g_affA[2][64];    // BN affine scale per layer (overwritten)
__device__ float    g_affB[2][64];    // BN affine shift per layer (overwritten)

// ---------------- launch 0: degree histogram ∥ (wfrag + gstart + BN affine) ----------------
__global__ void k_degree_init(const int* __restrict__ ei, const int* __restrict__ batch,
                              const float* __restrict__ W1, const float* __restrict__ W2,
                              const float* __restrict__ b1,
                              const float* __restrict__ bn1g, const float* __restrict__ bn1b,
                              const float* __restrict__ bn1m, const float* __restrict__ bn1v,
                              const float* __restrict__ b2,
                              const float* __restrict__ bn2g, const float* __restrict__ bn2b,
                              const float* __restrict__ bn2m, const float* __restrict__ bn2v) {
    int t = threadIdx.x;
    if (blockIdx.x < NB_DEG) {
        int e = blockIdx.x * 256 + t;
        if (e < EE / 4) {
            int4 c = ((const int4*)(ei + EE))[e];
            atomicAdd(&g_deg[c.x], 1);
            atomicAdd(&g_deg[c.y], 1);
            atomicAdd(&g_deg[c.z], 1);
            atomicAdd(&g_deg[c.w], 1);
        }
        return;
    }
    int i = (blockIdx.x - NB_DEG) * 256 + t;
    if (i < 4096) {
        int l = i >> 11;
        int o = i & 2047;
        const float* W = l ? W2 : W1;
        int reg = o & 1, lane = (o >> 1) & 31, nt = (o >> 6) & 7, ktp = o >> 9;
        int n = nt * 8 + (lane >> 2);
        int k = ktp * 16 + reg * 8 + (lane & 3) * 2;
        __half2 h = __floats2half2_rn(W[n * 64 + k], W[n * 64 + k + 1]);
        g_wfrag[l][o] = *(unsigned*)&h;
    }
    if (i < 128) {  // BN affine: A = g*rsqrt(v+eps); B = (bias-m)*A + b
        int l = i >> 6, c = i & 63;
        const float* bias = l ? b2 : b1;
        const float* bg = l ? bn2g : bn1g;
        const float* bb = l ? bn2b : bn1b;
        const float* bm = l ? bn2m : bn1m;
        const float* bv = l ? bn2v : bn1v;
        float A = bg[c] * rsqrtf(bv[c] + BN_EPS);
        g_affA[l][c] = A;
        g_affB[l][c] = (bias[c] - bm[c]) * A + bb[c];
    }
    if (i <= NN) {
        int prev = (i == 0) ? -1 : batch[i - 1];
        int cur  = (i < NN) ? batch[i] : GG;
        for (int g = prev + 1; g <= cur && g <= GG; g++) g_gstart[g] = i;
    }
}

// ---------------- launch 1: per-chunk scan + dinv; last block computes chunk prefixes ----------------
__global__ void k_scan_a() {
    __shared__ int sh[256];
    __shared__ int lastflag;
    int t = threadIdx.x;
    int base = blockIdx.x * 2048 + t * 8;
    int vals[8];
    int ts = 0;
#pragma unroll
    for (int j = 0; j < 8; j++) {
        int idx = base + j;
        vals[j] = (idx < NN) ? g_deg[idx] : 0;
        if (idx < NN) g_dinv[idx] = rsqrtf((float)(vals[j] + 1));
        ts += vals[j];
    }
    sh[t] = ts;
    __syncthreads();
#pragma unroll
    for (int d = 1; d < 256; d <<= 1) {
        int v = (t >= d) ? sh[t - d] : 0;
        __syncthreads();
        sh[t] += v;
        __syncthreads();
    }
    int excl = sh[t] - ts;
    int run = 0;
#pragma unroll
    for (int j = 0; j < 8; j++) {
        int idx = base + j;
        if (idx < NN) g_off[idx] = excl + run;
        run += vals[j];
    }
    if (t == 255) g_bsum[blockIdx.x] = sh[255];
    __threadfence();
    __syncthreads();
    if (t == 0) lastflag = (atomicAdd(&g_done, 1) == NB_SCAN - 1) ? 1 : 0;
    __syncthreads();
    if (!lastflag) return;
    __threadfence();
    __shared__ int sv[64];
    int v0 = 0;
    if (t < 64) {
        v0 = (t < NB_SCAN) ? g_bsum[t] : 0;
        sv[t] = v0;
    }
    __syncthreads();
#pragma unroll
    for (int d = 1; d < 64; d <<= 1) {
        int v = (t >= d && t < 64) ? sv[t - d] : 0;
        __syncthreads();
        if (t < 64) sv[t] += v;
        __syncthreads();
    }
    if (t < NB_SCAN) g_pref[t] = sv[t] - v0;
    if (t == 0) g_done = 0;
}

// ---------------- shared GEMM body: mma.sync m16n8k16 fp16 (fp32 accum) ----------------
template <bool FP16IN>
__device__ __forceinline__ void gemm_body(unsigned* shm, const void* __restrict__ Xin,
                                          const unsigned* __restrict__ wfrag,
                                          __half2* __restrict__ O, int base, int tid) {
    unsigned (*sA)[4][32][4] = (unsigned (*)[4][32][4])shm;
    unsigned* sB = shm + 4096;

#pragma unroll
    for (int i = tid; i < 512; i += 256)
        ((uint4*)sB)[i] = ((const uint4*)wfrag)[i];

    if (FP16IN) {
        const uint4* X = (const uint4*)Xin;
        for (int i = tid; i < 1024; i += 256) {
            int r = i >> 3, j = i & 7;
            int R = base + r;
            uint4 v = make_uint4(0u, 0u, 0u, 0u);
            if (R < NN) v = X[(size_t)R * 8 + j];
            int w8 = r >> 4, rr = r & 15;
            int ktp = j >> 1;
            int reg = ((rr >> 3) & 1) | ((j & 1) << 1);
            int lb = (rr & 7) * 4;
            sA[w8][ktp][lb + 0][reg] = v.x;
            sA[w8][ktp][lb + 1][reg] = v.y;
            sA[w8][ktp][lb + 2][reg] = v.z;
            sA[w8][ktp][lb + 3][reg] = v.w;
        }
    } else {
        const float4* X = (const float4*)Xin;
        for (int i = tid; i < 2048; i += 256) {
            int r = i >> 4, j = i & 15;
            int R = base + r;
            float4 v = make_float4(0.f, 0.f, 0.f, 0.f);
            if (R < NN) v = X[(size_t)R * 16 + j];
            int w8 = r >> 4, rr = r & 15;
            int ktp = j >> 2, jj = j & 3;
            int reg = ((rr >> 3) & 1) | ((jj >> 1) << 1);
            int t0 = (2 * jj) & 3;
            int lb = (rr & 7) * 4;
            __half2 h0 = __floats2half2_rn(v.x, v.y);
            __half2 h1 = __floats2half2_rn(v.z, v.w);
            sA[w8][ktp][lb + t0][reg]     = *(unsigned*)&h0;
            sA[w8][ktp][lb + t0 + 1][reg] = *(unsigned*)&h1;
        }
    }
    __syncthreads();

    int lane = tid & 31;
    int w = tid >> 5;
    float d[8][4];
#pragma unroll
    for (int nt = 0; nt < 8; nt++)
#pragma unroll
        for (int j = 0; j < 4; j++) d[nt][j] = 0.f;

#pragma unroll
    for (int ktp = 0; ktp < 4; ktp++) {
        uint4 a = *(const uint4*)&sA[w][ktp][lane][0];
#pragma unroll
        for (int nt = 0; nt < 8; nt++) {
            uint2 b = *(const uint2*)&sB[(((ktp << 3) + nt) << 6) + (lane << 1)];
            asm volatile(
                "mma.sync.aligned.m16n8k16.row.col.f32.f16.f16.f32 "
                "{%0,%1,%2,%3}, {%4,%5,%6,%7}, {%8,%9}, {%0,%1,%2,%3};"
                : "+f"(d[nt][0]), "+f"(d[nt][1]), "+f"(d[nt][2]), "+f"(d[nt][3])
                : "r"(a.x), "r"(a.y), "r"(a.z), "r"(a.w), "r"(b.x), "r"(b.y));
        }
    }

    __syncthreads();
    unsigned* sD = shm;
    int g = lane >> 2, t4 = lane & 3;
    int rl0 = w * 16 + g, rl1 = rl0 + 8;
    int row0 = base + rl0, row1 = base + rl1;
    float dv0 = (row0 < NN) ? g_dinv[row0] : 0.f;
    float dv1 = (row1 < NN) ? g_dinv[row1] : 0.f;
#pragma unroll
    for (int nt = 0; nt < 8; nt++) {
        int cp = nt * 4 + t4;
        __half2 h0 = __floats2half2_rn(d[nt][0] * dv0, d[nt][1] * dv0);
        __half2 h1 = __floats2half2_rn(d[nt][2] * dv1, d[nt][3] * dv1);
        sD[rl0 * 36 + cp] = *(unsigned*)&h0;
        sD[rl1 * 36 + cp] = *(unsigned*)&h1;
    }
    __syncthreads();
#pragma unroll
    for (int i = tid; i < 1024; i += 256) {
        int r = i >> 3, col = i & 7;
        int R = base + r;
        if (R < NN)
            ((uint4*)O)[(size_t)R * 8 + col] = *(const uint4*)&sD[r * 36 + col * 4];
    }
}

// ---------------- launch 2: gemm1 ∥ CSR scatter (8 edges/thread) ----------------
__global__ void __launch_bounds__(256) k_gemm1_scatter(
    const float4* __restrict__ X, const unsigned* __restrict__ wfrag,
    __half2* __restrict__ O, const int* __restrict__ ei) {
    __shared__ unsigned shm[6144];
    if (blockIdx.x >= NB_G1) {
        int e = (blockIdx.x - NB_G1) * 256 + threadIdx.x;
        if (e < EE / 8) {
            const int4* r4 = (const int4*)ei;
            const int4* c4 = (const int4*)(ei + EE);
            int4 r0 = r4[2 * e], r1 = r4[2 * e + 1];
            int4 c0 = c4[2 * e], c1 = c4[2 * e + 1];
            g_csr[atomicAdd(&g_off[c0.x], 1) + g_pref[c0.x >> 11]] = r0.x;
            g_csr[atomicAdd(&g_off[c0.y], 1) + g_pref[c0.y >> 11]] = r0.y;
            g_csr[atomicAdd(&g_off[c0.z], 1) + g_pref[c0.z >> 11]] = r0.z;
            g_csr[atomicAdd(&g_off[c0.w], 1) + g_pref[c0.w >> 11]] = r0.w;
            g_csr[atomicAdd(&g_off[c1.x], 1) + g_pref[c1.x >> 11]] = r1.x;
            g_csr[atomicAdd(&g_off[c1.y], 1) + g_pref[c1.y >> 11]] = r1.y;
            g_csr[atomicAdd(&g_off[c1.z], 1) + g_pref[c1.z >> 11]] = r1.z;
            g_csr[atomicAdd(&g_off[c1.w], 1) + g_pref[c1.w >> 11]] = r1.w;
        }
        return;
    }
    gemm_body<false>(shm, X, wfrag, O, blockIdx.x * 128, threadIdx.x);
}

// ---------------- launch 4: gemm2 (fp16 input) ----------------
__global__ void __launch_bounds__(256) k_gemm2(
    const __half2* __restrict__ X, const unsigned* __restrict__ wfrag,
    __half2* __restrict__ O) {
    __shared__ unsigned shm[6144];
    gemm_body<true>(shm, X, wfrag, O, blockIdx.x * 128, threadIdx.x);
}

// ---------------- aggregation: 2 nodes/warp, 4 channels (uint2) per lane ----------------
// half = lane/16 selects the node; lane sl = lane&15 owns channels 4sl..4sl+3.
// fp16 depth-2 tree + fp32 acc; BN affine precomputed (A, B). Predicated tail via
// per-lane cnt (hardware masks the shorter half-warp; cost = max of 2 degrees).
template <bool POOL, int NODES_PER_BLK>
__global__ void k_agg(const __half2* __restrict__ hs, __half2* __restrict__ out,
                      const int* __restrict__ batch,
                      const float* __restrict__ affA, const float* __restrict__ affB) {
    __shared__ float sp[2][64];
    int t = threadIdx.x;
    int w0 = blockIdx.x * NODES_PER_BLK;
    int gid0 = 0, gidL = 0;
    if (POOL) {
        if (t < 128) sp[t >> 6][t & 63] = 0.f;
        gid0 = batch[w0];
        gidL = batch[w0 + NODES_PER_BLK - 1];
        __syncthreads();
    }
    int warp = t >> 5;
    int lane = t & 31;
    int half = lane >> 4;
    int sl = lane & 15;
    int node = w0 + 2 * warp + half;   // NN divisible by NODES_PER_BLK -> always valid

    const uint2* hv = (const uint2*)hs;  // 16 uint2 per row
    uint2 self = hv[(size_t)node * 16 + sl];
    float2 f0 = __half22float2(*(__half2*)&self.x);
    float2 f1 = __half22float2(*(__half2*)&self.y);
    float a0 = f0.x, a1 = f0.y, a2 = f1.x, a3 = f1.y;

    int cnt = g_deg[node];
    int s = g_off[node] + g_pref[node >> 11] - cnt;
    int i = 0;
    for (; i + 4 <= cnt; i += 4) {
        int r0 = g_csr[s + i + 0];
        int r1 = g_csr[s + i + 1];
        int r2 = g_csr[s + i + 2];
        int r3 = g_csr[s + i + 3];
        uint2 u0 = hv[(size_t)r0 * 16 + sl];
        uint2 u1 = hv[(size_t)r1 * 16 + sl];
        uint2 u2 = hv[(size_t)r2 * 16 + sl];
        uint2 u3 = hv[(size_t)r3 * 16 + sl];
        __half2 px = __hadd2(__hadd2(*(__half2*)&u0.x, *(__half2*)&u1.x),
                             __hadd2(*(__half2*)&u2.x, *(__half2*)&u3.x));
        __half2 py = __hadd2(__hadd2(*(__half2*)&u0.y, *(__half2*)&u1.y),
                             __hadd2(*(__half2*)&u2.y, *(__half2*)&u3.y));
        float2 gx = __half22float2(px);
        float2 gy = __half22float2(py);
        a0 += gx.x; a1 += gx.y; a2 += gy.x; a3 += gy.y;
    }
    for (; i < cnt; i++) {
        uint2 u = hv[(size_t)g_csr[s + i] * 16 + sl];
        float2 gx = __half22float2(*(__half2*)&u.x);
        float2 gy = __half22float2(*(__half2*)&u.y);
        a0 += gx.x; a1 += gx.y; a2 += gy.x; a3 += gy.y;
    }
    if (POOL && lane == half * 16) g_deg[node] = 0;  // self-restore (once per node)

    float dv = g_dinv[node];
    int c0 = 4 * sl;
    float4 A = *(const float4*)&affA[c0];
    float4 B = *(const float4*)&affB[c0];
    float o0 = fmaxf(0.f, fmaf(a0 * dv, A.x, B.x));
    float o1 = fmaxf(0.f, fmaf(a1 * dv, A.y, B.y));
    float o2 = fmaxf(0.f, fmaf(a2 * dv, A.z, B.z));
    float o3 = fmaxf(0.f, fmaf(a3 * dv, A.w, B.w));

    if (!POOL) {
        __half2 h0 = __floats2half2_rn(o0, o1);
        __half2 h1 = __floats2half2_rn(o2, o3);
        uint2 st;
        st.x = *(unsigned*)&h0;
        st.y = *(unsigned*)&h1;
        ((uint2*)out)[(size_t)node * 16 + sl] = st;
    } else {
        int gid = batch[node];
        int slot = gid - gid0;
        if (slot < 2) {
            atomicAdd(&sp[slot][c0 + 0], o0);
            atomicAdd(&sp[slot][c0 + 1], o1);
            atomicAdd(&sp[slot][c0 + 2], o2);
            atomicAdd(&sp[slot][c0 + 3], o3);
        } else {
            atomicAdd(&g_pool[gid * 64 + c0 + 0], o0);
            atomicAdd(&g_pool[gid * 64 + c0 + 1], o1);
            atomicAdd(&g_pool[gid * 64 + c0 + 2], o2);
            atomicAdd(&g_pool[gid * 64 + c0 + 3], o3);
        }
        __syncthreads();
        if (t < 128) {
            int s2 = t >> 6, ch = t & 63;
            int gg = gid0 + s2;
            if (gg <= gidL && gg < GG) atomicAdd(&g_pool[gg * 64 + ch], sp[s2][ch]);
        }
    }
}

// ---------------- MLP head (+ g_pool self-restore) ----------------
__global__ void k_head(const float* __restrict__ l1W, const float* __restrict__ l1b,
                       const float* __restrict__ l2W, const float* __restrict__ l2b,
                       float* __restrict__ out) {
    __shared__ float sW1[32 * 64];
    __shared__ float sW2[32];
    __shared__ float sB1[32];
    int t = threadIdx.x;  // 64 threads
    for (int i = t; i < 2048; i += 64) sW1[i] = l1W[i];
    if (t < 32) { sW2[t] = l2W[t]; sB1[t] = l1b[t]; }
    __syncthreads();
    if (t < GG) {
        int g = t;
        int cnt = g_gstart[g + 1] - g_gstart[g];
        float inv = 1.f / fmaxf((float)cnt, 1.f);
        float p[64];
#pragma unroll
        for (int k = 0; k < 64; k++) p[k] = g_pool[g * 64 + k] * inv;
        float o = l2b[0];
#pragma unroll 4
        for (int j = 0; j < 32; j++) {
            float hsum = sB1[j];
#pragma unroll
            for (int k = 0; k < 64; k++) hsum = fmaf(p[k], sW1[j * 64 + k], hsum);
            o = fmaf(fmaxf(hsum, 0.f), sW2[j], o);
        }
        out[g] = o;
    }
    __syncthreads();
    for (int i = t; i < GG * 64; i += 64) g_pool[i] = 0.f;  // self-restore
}

// ---------------- launch ----------------
extern "C" void kernel_launch(void* const* d_in, const int* in_sizes, int n_in,
                              void* d_out, int out_size) {
    const float* x      = (const float*)d_in[0];
    const int*   ei     = (const int*)d_in[1];
    const int*   batch  = (const int*)d_in[2];
    const float* W1     = (const float*)d_in[3];
    const float* b1     = (const float*)d_in[4];
    const float* W2     = (const float*)d_in[5];
    const float* b2     = (const float*)d_in[6];
    const float* bn1g   = (const float*)d_in[7];
    const float* bn1b   = (const float*)d_in[8];
    const float* bn1m   = (const float*)d_in[9];
    const float* bn1v   = (const float*)d_in[10];
    const float* bn2g   = (const float*)d_in[11];
    const float* bn2b   = (const float*)d_in[12];
    const float* bn2m   = (const float*)d_in[13];
    const float* bn2v   = (const float*)d_in[14];
    const float* l1W    = (const float*)d_in[15];
    const float* l1b    = (const float*)d_in[16];
    const float* l2W    = (const float*)d_in[17];
    const float* l2b    = (const float*)d_in[18];
    float* out = (float*)d_out;

    __half2 *hs, *hb;
    unsigned* wfrag;
    float *affA, *affB;
    cudaGetSymbolAddress((void**)&hs, g_hs);
    cudaGetSymbolAddress((void**)&hb, g_hb);
    cudaGetSymbolAddress((void**)&wfrag, g_wfrag);
    cudaGetSymbolAddress((void**)&affA, g_affA);
    cudaGetSymbolAddress((void**)&affB, g_affB);

    k_degree_init<<<NB_DEG + NB_AUX, 256>>>(ei, batch, W1, W2,
                                            b1, bn1g, bn1b, bn1m, bn1v,
                                            b2, bn2g, bn2b, bn2m, bn2v);          // 0
    k_scan_a<<<NB_SCAN, 256>>>();                                                  // 1
    k_gemm1_scatter<<<NB_G1 + NB_SCT, 256>>>((const float4*)x, wfrag, hs, ei);     // 2
    // layer 1: agg -> fp16 hb   (16 nodes / 256-thr block)
    k_agg<false, 16><<<NN / 16, 256>>>(hs, hb, batch, affA, affB);                 // 3 <- ncu
    k_gemm2<<<NB_G1, 256>>>(hb, wfrag + 2048, hs);                                 // 4
    // layer 2: agg + pooling    (32 nodes / 512-thr block)
    k_agg<true, 32><<<NN / 32, 512>>>(hs, nullptr, batch, affA + 64, affB + 64);   // 5
    k_head<<<1, 64>>>(l1W, l1b, l2W, l2b, out);                                    // 6
}